// round 3
// baseline (speedup 1.0000x reference)
#include <cuda_runtime.h>

#define DIM 16384
#define OUTN 1000
#define OUT_BASE (DIM - OUTN)   /* 15384, multiple of 4 */
#define TPB 256

// 26 fused two-qubit gate matrices (4x4 each), indexed [stage*7 + pair]*16
__device__ float d_G[448];

// ---------------------------------------------------------------------------
// Prep: build fused gates. Gate on bit pair (hi=lo+1, lo):
//   G = (RY(th_hi) (x) RY(th_lo)) * CZ      [stage 0 additionally * bias RYs]
// m index = 2*bit_hi + bit_lo. qubit w <-> bit (13-w).
// even stage: lo = 2p   -> circuit qubit i = 12-2p
// odd  stage: lo = 2p+1 -> circuit qubit i = 11-2p
// ---------------------------------------------------------------------------
__global__ void qnn_prep(const float* __restrict__ w, const float* __restrict__ bias) {
    int g = threadIdx.x;
    if (g >= 26) return;
    int stage, p;
    if (g < 7)       { stage = 0; p = g; }
    else if (g < 13) { stage = 1; p = g - 7; }
    else if (g < 20) { stage = 2; p = g - 13; }
    else             { stage = 3; p = g - 20; }
    int l = stage >> 1;
    int par = stage & 1;
    int i = par ? (11 - 2 * p) : (12 - 2 * p);

    float thH = 0.5f * w[l * 26 + i * 2 + 0];
    float thL = 0.5f * w[l * 26 + i * 2 + 1];
    float A[4] = { cosf(thH), -sinf(thH), sinf(thH), cosf(thH) };
    float B[4] = { cosf(thL), -sinf(thL), sinf(thL), cosf(thL) };
    float G[16];
    for (int mp = 0; mp < 4; mp++)
        for (int m = 0; m < 4; m++) {
            float v = A[(mp >> 1) * 2 + (m >> 1)] * B[(mp & 1) * 2 + (m & 1)];
            G[mp * 4 + m] = (m == 3) ? -v : v;   // CZ applied first
        }
    if (stage == 0) {
        float bH = 0.5f * bias[i], bL = 0.5f * bias[i + 1];
        float Ab[4] = { cosf(bH), -sinf(bH), sinf(bH), cosf(bH) };
        float Bb[4] = { cosf(bL), -sinf(bL), sinf(bL), cosf(bL) };
        float Gb[16];
        for (int mp = 0; mp < 4; mp++)
            for (int m = 0; m < 4; m++)
                Gb[mp * 4 + m] = Ab[(mp >> 1) * 2 + (m >> 1)] * Bb[(mp & 1) * 2 + (m & 1)];
        float GG[16];
        for (int a = 0; a < 4; a++)
            for (int c = 0; c < 4; c++) {
                float s = 0.f;
                for (int k = 0; k < 4; k++) s += G[a * 4 + k] * Gb[k * 4 + c];
                GG[a * 4 + c] = s;               // apply bias first: G * Gb
            }
        for (int x = 0; x < 16; x++) G[x] = GG[x];
    }
    for (int x = 0; x < 16; x++) d_G[(stage * 7 + p) * 16 + x] = G[x];
}

// ---------------------------------------------------------------------------
// Main kernel helpers
// ---------------------------------------------------------------------------
__device__ __forceinline__ int swz(int P) { return P ^ ((P >> 4) & 15); }

struct G16 { float g[16]; };

__device__ __forceinline__ G16 ldGm(const float* sG, int i) {
    G16 r;
    #pragma unroll
    for (int x = 0; x < 16; x++) r.g[x] = sG[i * 16 + x];
    return r;
}

__device__ __forceinline__ void gate4(const G16& G, float& a, float& b, float& c, float& d) {
    float x = a, y = b, z = c, w = d;
    a = G.g[0]  * x + G.g[1]  * y + G.g[2]  * z + G.g[3]  * w;
    b = G.g[4]  * x + G.g[5]  * y + G.g[6]  * z + G.g[7]  * w;
    c = G.g[8]  * x + G.g[9]  * y + G.g[10] * z + G.g[11] * w;
    d = G.g[12] * x + G.g[13] * y + G.g[14] * z + G.g[15] * w;
}

// gate on vector-lane bits (1,0): m = j & 3
__device__ __forceinline__ void op_vec(const G16& G, float4 v[16]) {
    #pragma unroll
    for (int q = 0; q < 16; q++) gate4(G, v[q].x, v[q].y, v[q].z, v[q].w);
}
// gate on quad bits (qb1,qb0): m = q & 3
__device__ __forceinline__ void op_qlow(const G16& G, float4 v[16]) {
    #pragma unroll
    for (int h = 0; h < 16; h += 4) {
        gate4(G, v[h].x, v[h+1].x, v[h+2].x, v[h+3].x);
        gate4(G, v[h].y, v[h+1].y, v[h+2].y, v[h+3].y);
        gate4(G, v[h].z, v[h+1].z, v[h+2].z, v[h+3].z);
        gate4(G, v[h].w, v[h+1].w, v[h+2].w, v[h+3].w);
    }
}
// gate on quad bits (qb3,qb2): m = q >> 2
__device__ __forceinline__ void op_qhigh(const G16& G, float4 v[16]) {
    #pragma unroll
    for (int j = 0; j < 4; j++) {
        gate4(G, v[j].x, v[j+4].x, v[j+8].x, v[j+12].x);
        gate4(G, v[j].y, v[j+4].y, v[j+8].y, v[j+12].y);
        gate4(G, v[j].z, v[j+4].z, v[j+8].z, v[j+12].z);
        gate4(G, v[j].w, v[j+4].w, v[j+8].w, v[j+12].w);
    }
}
// gate (2,1) on LA tile: hi = q bit0, lo = lane bit1
__device__ __forceinline__ void op_g21(const G16& G, float4 v[16]) {
    #pragma unroll
    for (int h = 0; h < 16; h += 2) {
        gate4(G, v[h].x, v[h].z, v[h+1].x, v[h+1].z);
        gate4(G, v[h].y, v[h].w, v[h+1].y, v[h+1].w);
    }
}
// gate (4,3) on LA tile: hi = q bit2, lo = q bit1
__device__ __forceinline__ void op_g43(const G16& G, float4 v[16]) {
    #pragma unroll
    for (int j3 = 0; j3 < 2; j3++)
        #pragma unroll
        for (int j0 = 0; j0 < 2; j0++) {
            int b0 = j0 + 8 * j3;
            gate4(G, v[b0].x, v[b0+2].x, v[b0+4].x, v[b0+6].x);
            gate4(G, v[b0].y, v[b0+2].y, v[b0+4].y, v[b0+6].y);
            gate4(G, v[b0].z, v[b0+2].z, v[b0+4].z, v[b0+6].z);
            gate4(G, v[b0].w, v[b0+2].w, v[b0+4].w, v[b0+6].w);
        }
}

template<int QS>
__device__ __forceinline__ void ldv(const float4* s4, int tb, float4 v[16]) {
    #pragma unroll
    for (int q = 0; q < 16; q++) v[q] = s4[swz(tb | (q << QS))];
}
template<int QS>
__device__ __forceinline__ void stv(float4* s4, int tb, const float4 v[16]) {
    #pragma unroll
    for (int q = 0; q < 16; q++) s4[swz(tb | (q << QS))] = v[q];
}

// ---------------------------------------------------------------------------
// Main kernel: 1 CTA per batch row, state in SMEM, 13 passes total
// ---------------------------------------------------------------------------
__global__ void __launch_bounds__(TPB) qnn_main(const float* __restrict__ in,
                                                float* __restrict__ out) {
    extern __shared__ float sm[];
    float4* s4 = (float4*)sm;
    float* sG   = sm + DIM;       // 448 floats
    float* red  = sG + 448;       // 8 floats
    float* pinv = red + 8;        // 1 float
    const int t = threadIdx.x;
    const int b = blockIdx.x;

    for (int x = t; x < 448; x += TPB) sG[x] = d_G[x];

    // pass 0: coalesced global load + sum of squares
    const float4* g4 = (const float4*)(in + (size_t)b * DIM);
    float ss = 0.f;
    #pragma unroll
    for (int q = 0; q < 16; q++) {
        int idx = t + q * TPB;
        float4 d = g4[idx];
        ss += d.x * d.x + d.y * d.y + d.z * d.z + d.w * d.w;
        s4[swz(idx)] = d;
    }
    #pragma unroll
    for (int o = 16; o; o >>= 1) ss += __shfl_xor_sync(0xffffffffu, ss, o);
    if ((t & 31) == 0) red[t >> 5] = ss;
    __syncthreads();
    if (t == 0) {
        float tot = 0.f;
        #pragma unroll
        for (int k = 0; k < 8; k++) tot += red[k];
        pinv[0] = 1.0f / tot;   // made visible by the pass-1 __syncthreads
    }

    // tile base addresses (float4-index space, 12 bits = amp bits 2..13)
    const int tbLA = t << 4;                          // local amp bits {0..5}
    const int tbBE = (t & 15) | ((t >> 4) << 8);      // local {0,1,6,7,8,9}
    const int tbCE = t;                               // local {0,1,10,11,12,13}
    const int tbBO = (t & 7) | ((t >> 3) << 7);       // local {0,1,5,6,7,8}
    const int tbCO = (t & 127) | ((t >> 7) << 11);    // local {0,1,9,10,11,12}

    float4 v[16];

    // ---- stage 0: bias + L0 even: gates (1,0)(3,2)(5,4)(7,6)(9,8)(11,10)(13,12)
    ldv<0>(s4, tbLA, v);
    { G16 g = ldGm(sG, 0); op_vec(g, v); }
    { G16 g = ldGm(sG, 1); op_qlow(g, v); }
    { G16 g = ldGm(sG, 2); op_qhigh(g, v); }
    stv<0>(s4, tbLA, v);
    __syncthreads();

    ldv<4>(s4, tbBE, v);
    { G16 g = ldGm(sG, 3); op_qlow(g, v); }
    { G16 g = ldGm(sG, 4); op_qhigh(g, v); }
    stv<4>(s4, tbBE, v);
    __syncthreads();

    ldv<8>(s4, tbCE, v);
    { G16 g = ldGm(sG, 5); op_qlow(g, v); }
    { G16 g = ldGm(sG, 6); op_qhigh(g, v); }
    stv<8>(s4, tbCE, v);
    __syncthreads();

    // ---- stage 1: L0 odd: gates (2,1)(4,3)(6,5)(8,7)(10,9)(12,11)
    ldv<0>(s4, tbLA, v);
    { G16 g = ldGm(sG, 7); op_g21(g, v); }
    { G16 g = ldGm(sG, 8); op_g43(g, v); }
    stv<0>(s4, tbLA, v);
    __syncthreads();

    ldv<3>(s4, tbBO, v);
    { G16 g = ldGm(sG, 9);  op_qlow(g, v); }
    { G16 g = ldGm(sG, 10); op_qhigh(g, v); }
    stv<3>(s4, tbBO, v);
    __syncthreads();

    ldv<7>(s4, tbCO, v);
    { G16 g = ldGm(sG, 11); op_qlow(g, v); }
    { G16 g = ldGm(sG, 12); op_qhigh(g, v); }
    stv<7>(s4, tbCO, v);
    __syncthreads();

    // ---- stage 2: L1 even
    ldv<0>(s4, tbLA, v);
    { G16 g = ldGm(sG, 14); op_vec(g, v); }
    { G16 g = ldGm(sG, 15); op_qlow(g, v); }
    { G16 g = ldGm(sG, 16); op_qhigh(g, v); }
    stv<0>(s4, tbLA, v);
    __syncthreads();

    ldv<4>(s4, tbBE, v);
    { G16 g = ldGm(sG, 17); op_qlow(g, v); }
    { G16 g = ldGm(sG, 18); op_qhigh(g, v); }
    stv<4>(s4, tbBE, v);
    __syncthreads();

    ldv<8>(s4, tbCE, v);
    { G16 g = ldGm(sG, 19); op_qlow(g, v); }
    { G16 g = ldGm(sG, 20); op_qhigh(g, v); }
    stv<8>(s4, tbCE, v);
    __syncthreads();

    // ---- stage 3: L1 odd
    ldv<0>(s4, tbLA, v);
    { G16 g = ldGm(sG, 21); op_g21(g, v); }
    { G16 g = ldGm(sG, 22); op_g43(g, v); }
    stv<0>(s4, tbLA, v);
    __syncthreads();

    ldv<3>(s4, tbBO, v);
    { G16 g = ldGm(sG, 23); op_qlow(g, v); }
    { G16 g = ldGm(sG, 24); op_qhigh(g, v); }
    stv<3>(s4, tbBO, v);
    __syncthreads();

    // final pass: last two gates + squared/normalized output (no store back)
    ldv<7>(s4, tbCO, v);
    { G16 g = ldGm(sG, 25); op_qlow(g, v); }
    { G16 g = ldGm(sG, 26); op_qhigh(g, v); }
    {
        float inv = pinv[0];
        float* ob = out + (size_t)b * OUTN;
        #pragma unroll
        for (int q = 0; q < 16; q++) {
            int j = (tbCO | (q << 7)) << 2;
            if (j >= OUT_BASE) {
                float4 r;
                r.x = v[q].x * v[q].x * inv;
                r.y = v[q].y * v[q].y * inv;
                r.z = v[q].z * v[q].z * inv;
                r.w = v[q].w * v[q].w * inv;
                *(float4*)(ob + (j - OUT_BASE)) = r;
            }
        }
    }
}

extern "C" void kernel_launch(void* const* d_in, const int* in_sizes, int n_in,
                              void* d_out, int out_size) {
    const float* in   = (const float*)d_in[0];
    const float* w    = (const float*)d_in[1];
    const float* bias = (const float*)d_in[2];
    float* out = (float*)d_out;
    int B = in_sizes[0] / DIM;   // 512

    const int smem_bytes = (DIM + 448 + 8 + 4) * (int)sizeof(float);  // ~67 KB
    cudaFuncSetAttribute(qnn_main, cudaFuncAttributeMaxDynamicSharedMemorySize, smem_bytes);

    qnn_prep<<<1, 32>>>(w, bias);
    qnn_main<<<B, TPB, smem_bytes>>>(in, out);
}

// round 4
// speedup vs baseline: 1.0219x; 1.0219x over previous
#include <cuda_runtime.h>

#define DIM 16384
#define OUTN 1000
#define OUT_BASE (DIM - OUTN)   /* 15384, multiple of 4 */
#define TPB 256

typedef unsigned long long ull;

// 26 fused two-qubit gate matrices (4x4 each), indexed [stage*7 + pair]*16
__device__ float d_G[448];

// ---------------------------------------------------------------------------
// Prep: build fused gates (unchanged from R3, verified correct).
// ---------------------------------------------------------------------------
__global__ void qnn_prep(const float* __restrict__ w, const float* __restrict__ bias) {
    int g = threadIdx.x;
    if (g >= 26) return;
    int stage, p;
    if (g < 7)       { stage = 0; p = g; }
    else if (g < 13) { stage = 1; p = g - 7; }
    else if (g < 20) { stage = 2; p = g - 13; }
    else             { stage = 3; p = g - 20; }
    int l = stage >> 1;
    int par = stage & 1;
    int i = par ? (11 - 2 * p) : (12 - 2 * p);

    float thH = 0.5f * w[l * 26 + i * 2 + 0];
    float thL = 0.5f * w[l * 26 + i * 2 + 1];
    float A[4] = { cosf(thH), -sinf(thH), sinf(thH), cosf(thH) };
    float B[4] = { cosf(thL), -sinf(thL), sinf(thL), cosf(thL) };
    float G[16];
    for (int mp = 0; mp < 4; mp++)
        for (int m = 0; m < 4; m++) {
            float v = A[(mp >> 1) * 2 + (m >> 1)] * B[(mp & 1) * 2 + (m & 1)];
            G[mp * 4 + m] = (m == 3) ? -v : v;   // CZ applied first
        }
    if (stage == 0) {
        float bH = 0.5f * bias[i], bL = 0.5f * bias[i + 1];
        float Ab[4] = { cosf(bH), -sinf(bH), sinf(bH), cosf(bH) };
        float Bb[4] = { cosf(bL), -sinf(bL), sinf(bL), cosf(bL) };
        float Gb[16];
        for (int mp = 0; mp < 4; mp++)
            for (int m = 0; m < 4; m++)
                Gb[mp * 4 + m] = Ab[(mp >> 1) * 2 + (m >> 1)] * Bb[(mp & 1) * 2 + (m & 1)];
        float GG[16];
        for (int a = 0; a < 4; a++)
            for (int c = 0; c < 4; c++) {
                float s = 0.f;
                for (int k = 0; k < 4; k++) s += G[a * 4 + k] * Gb[k * 4 + c];
                GG[a * 4 + c] = s;               // apply bias first: G * Gb
            }
        for (int x = 0; x < 16; x++) G[x] = GG[x];
    }
    for (int x = 0; x < 16; x++) d_G[(stage * 7 + p) * 16 + x] = G[x];
}

// ---------------------------------------------------------------------------
// Packed f32x2 helpers (FFMA2 path — not emitted by ptxas from C++)
// ---------------------------------------------------------------------------
__device__ __forceinline__ ull f2mul(ull a, ull b) {
    ull d; asm("mul.rn.f32x2 %0, %1, %2;" : "=l"(d) : "l"(a), "l"(b)); return d;
}
__device__ __forceinline__ ull f2fma(ull a, ull b, ull c) {
    ull d; asm("fma.rn.f32x2 %0, %1, %2, %3;" : "=l"(d) : "l"(a), "l"(b), "l"(c)); return d;
}
__device__ __forceinline__ void up2(ull a, float& x, float& y) {
    asm("mov.b64 {%0, %1}, %2;" : "=f"(x), "=f"(y) : "l"(a));
}
__device__ __forceinline__ ull pk2(float x, float y) {
    ull a; asm("mov.b64 %0, {%1, %2};" : "=l"(a) : "f"(x), "f"(y)); return a;
}

__device__ __forceinline__ int swz(int P) { return P ^ ((P >> 4) & 15); }

struct G16  { float g[16]; };  // scalar gate (bit-(1,0) gates only)
struct G16P { ull   g[16]; };  // splatted (g,g) packed gate

__device__ __forceinline__ G16 ldGm(const float* sG, int i) {
    G16 r;
    #pragma unroll
    for (int x = 0; x < 16; x++) r.g[x] = sG[i * 16 + x];
    return r;
}
__device__ __forceinline__ G16P ldGp(const ull* sGp, int i) {
    G16P r;
    #pragma unroll
    for (int x = 0; x < 16; x++) r.g[x] = sGp[i * 16 + x];
    return r;
}

__device__ __forceinline__ void gate4(const G16& G, float& a, float& b, float& c, float& d) {
    float x = a, y = b, z = c, w = d;
    a = G.g[0]  * x + G.g[1]  * y + G.g[2]  * z + G.g[3]  * w;
    b = G.g[4]  * x + G.g[5]  * y + G.g[6]  * z + G.g[7]  * w;
    c = G.g[8]  * x + G.g[9]  * y + G.g[10] * z + G.g[11] * w;
    d = G.g[12] * x + G.g[13] * y + G.g[14] * z + G.g[15] * w;
}

// packed gate4: each ull carries two independent scalar lanes
__device__ __forceinline__ void gate4p(const G16P& G, ull& a, ull& b, ull& c, ull& d) {
    ull x = a, y = b, z = c, w = d;
    a = f2fma(G.g[3],  w, f2fma(G.g[2],  z, f2fma(G.g[1],  y, f2mul(G.g[0],  x))));
    b = f2fma(G.g[7],  w, f2fma(G.g[6],  z, f2fma(G.g[5],  y, f2mul(G.g[4],  x))));
    c = f2fma(G.g[11], w, f2fma(G.g[10], z, f2fma(G.g[9],  y, f2mul(G.g[8],  x))));
    d = f2fma(G.g[15], w, f2fma(G.g[14], z, f2fma(G.g[13], y, f2mul(G.g[12], x))));
}

// state tile: ulonglong2 v[16]; v[q].x = (amp0,amp1), v[q].y = (amp2,amp3)

// gate on lane bits (1,0): mixes within the float4 -> scalar path
__device__ __forceinline__ void op_vecS(const G16& G, ulonglong2 v[16]) {
    #pragma unroll
    for (int q = 0; q < 16; q++) {
        float a, b, c, d;
        up2(v[q].x, a, b); up2(v[q].y, c, d);
        gate4(G, a, b, c, d);
        v[q].x = pk2(a, b); v[q].y = pk2(c, d);
    }
}
// gate on quad bits (qb1,qb0)
__device__ __forceinline__ void op_qlowP(const G16P& G, ulonglong2 v[16]) {
    #pragma unroll
    for (int h = 0; h < 16; h += 4) {
        gate4p(G, v[h].x, v[h+1].x, v[h+2].x, v[h+3].x);
        gate4p(G, v[h].y, v[h+1].y, v[h+2].y, v[h+3].y);
    }
}
// gate on quad bits (qb3,qb2)
__device__ __forceinline__ void op_qhighP(const G16P& G, ulonglong2 v[16]) {
    #pragma unroll
    for (int j = 0; j < 4; j++) {
        gate4p(G, v[j].x, v[j+4].x, v[j+8].x, v[j+12].x);
        gate4p(G, v[j].y, v[j+4].y, v[j+8].y, v[j+12].y);
    }
}
// gate (2,1) on LA tile: hi = q bit0, lo = lane bit1
__device__ __forceinline__ void op_g21P(const G16P& G, ulonglong2 v[16]) {
    #pragma unroll
    for (int h = 0; h < 16; h += 2)
        gate4p(G, v[h].x, v[h].y, v[h+1].x, v[h+1].y);
}
// gate (4,3) on LA tile: hi = q bit2, lo = q bit1
__device__ __forceinline__ void op_g43P(const G16P& G, ulonglong2 v[16]) {
    #pragma unroll
    for (int j3 = 0; j3 < 2; j3++)
        #pragma unroll
        for (int j0 = 0; j0 < 2; j0++) {
            int b0 = j0 + 8 * j3;
            gate4p(G, v[b0].x, v[b0+2].x, v[b0+4].x, v[b0+6].x);
            gate4p(G, v[b0].y, v[b0+2].y, v[b0+4].y, v[b0+6].y);
        }
}

template<int QS>
__device__ __forceinline__ void ldv(const ulonglong2* s4, int tb, ulonglong2 v[16]) {
    #pragma unroll
    for (int q = 0; q < 16; q++) v[q] = s4[swz(tb | (q << QS))];
}
template<int QS>
__device__ __forceinline__ void stv(ulonglong2* s4, int tb, const ulonglong2 v[16]) {
    #pragma unroll
    for (int q = 0; q < 16; q++) s4[swz(tb | (q << QS))] = v[q];
}

// ---------------------------------------------------------------------------
// Main kernel: 1 CTA per batch row, state in SMEM, 13 passes, FFMA2 math.
// __launch_bounds__(TPB, 2): cap regs at 128 so 2 CTAs co-reside per SM.
// ---------------------------------------------------------------------------
__global__ void __launch_bounds__(TPB, 2) qnn_main(const float* __restrict__ in,
                                                   float* __restrict__ out) {
    extern __shared__ float sm[];
    ulonglong2* s4 = (ulonglong2*)sm;            // 16384 floats state
    ull*   sGp  = (ull*)(sm + DIM);              // 448 ull splatted gates (896 floats)
    float* sGs  = sm + DIM + 896;                // 448 floats scalar gates
    float* red  = sGs + 448;                     // 8 floats
    float* pinv = red + 8;                       // 1 float
    const int t = threadIdx.x;
    const int b = blockIdx.x;

    // stage gate tables into SMEM (scalar + splatted)
    for (int x = t; x < 448; x += TPB) {
        float g = d_G[x];
        sGs[x] = g;
        sGp[x] = pk2(g, g);
    }

    // pass 0: coalesced global load + packed sum of squares
    const ulonglong2* g4 = (const ulonglong2*)(in + (size_t)b * DIM);
    ull ssp = 0ull;  // packed (0.f, 0.f)
    #pragma unroll
    for (int q = 0; q < 16; q++) {
        int idx = t + q * TPB;
        ulonglong2 d = g4[idx];
        ssp = f2fma(d.x, d.x, ssp);
        ssp = f2fma(d.y, d.y, ssp);
        s4[swz(idx)] = d;
    }
    float s0, s1; up2(ssp, s0, s1);
    float ss = s0 + s1;
    #pragma unroll
    for (int o = 16; o; o >>= 1) ss += __shfl_xor_sync(0xffffffffu, ss, o);
    if ((t & 31) == 0) red[t >> 5] = ss;
    __syncthreads();
    if (t == 0) {
        float tot = 0.f;
        #pragma unroll
        for (int k = 0; k < 8; k++) tot += red[k];
        pinv[0] = 1.0f / tot;   // visible after the next __syncthreads
    }

    // tile base addresses (float4-index space, 12 bits = amp bits 2..13)
    const int tbLA = t << 4;                          // local amp bits {0..5}
    const int tbBE = (t & 15) | ((t >> 4) << 8);      // local {0,1,6,7,8,9}
    const int tbCE = t;                               // local {0,1,10,11,12,13}
    const int tbBO = (t & 7) | ((t >> 3) << 7);       // local {0,1,5,6,7,8}
    const int tbCO = (t & 127) | ((t >> 7) << 11);    // local {0,1,9,10,11,12}

    ulonglong2 v[16];

    // ---- stage 0: bias + L0 even: gates (1,0)(3,2)(5,4) | (7,6)(9,8) | (11,10)(13,12)
    ldv<0>(s4, tbLA, v);
    { G16  g = ldGm(sGs, 0); op_vecS(g, v); }
    { G16P g = ldGp(sGp, 1); op_qlowP(g, v); }
    { G16P g = ldGp(sGp, 2); op_qhighP(g, v); }
    stv<0>(s4, tbLA, v);
    __syncthreads();

    ldv<4>(s4, tbBE, v);
    { G16P g = ldGp(sGp, 3); op_qlowP(g, v); }
    { G16P g = ldGp(sGp, 4); op_qhighP(g, v); }
    stv<4>(s4, tbBE, v);
    __syncthreads();

    ldv<8>(s4, tbCE, v);
    { G16P g = ldGp(sGp, 5); op_qlowP(g, v); }
    { G16P g = ldGp(sGp, 6); op_qhighP(g, v); }
    stv<8>(s4, tbCE, v);
    __syncthreads();

    // ---- stage 1: L0 odd: gates (2,1)(4,3) | (6,5)(8,7) | (10,9)(12,11)
    ldv<0>(s4, tbLA, v);
    { G16P g = ldGp(sGp, 7); op_g21P(g, v); }
    { G16P g = ldGp(sGp, 8); op_g43P(g, v); }
    stv<0>(s4, tbLA, v);
    __syncthreads();

    ldv<3>(s4, tbBO, v);
    { G16P g = ldGp(sGp, 9);  op_qlowP(g, v); }
    { G16P g = ldGp(sGp, 10); op_qhighP(g, v); }
    stv<3>(s4, tbBO, v);
    __syncthreads();

    ldv<7>(s4, tbCO, v);
    { G16P g = ldGp(sGp, 11); op_qlowP(g, v); }
    { G16P g = ldGp(sGp, 12); op_qhighP(g, v); }
    stv<7>(s4, tbCO, v);
    __syncthreads();

    // ---- stage 2: L1 even
    ldv<0>(s4, tbLA, v);
    { G16  g = ldGm(sGs, 14); op_vecS(g, v); }
    { G16P g = ldGp(sGp, 15); op_qlowP(g, v); }
    { G16P g = ldGp(sGp, 16); op_qhighP(g, v); }
    stv<0>(s4, tbLA, v);
    __syncthreads();

    ldv<4>(s4, tbBE, v);
    { G16P g = ldGp(sGp, 17); op_qlowP(g, v); }
    { G16P g = ldGp(sGp, 18); op_qhighP(g, v); }
    stv<4>(s4, tbBE, v);
    __syncthreads();

    ldv<8>(s4, tbCE, v);
    { G16P g = ldGp(sGp, 19); op_qlowP(g, v); }
    { G16P g = ldGp(sGp, 20); op_qhighP(g, v); }
    stv<8>(s4, tbCE, v);
    __syncthreads();

    // ---- stage 3: L1 odd
    ldv<0>(s4, tbLA, v);
    { G16P g = ldGp(sGp, 21); op_g21P(g, v); }
    { G16P g = ldGp(sGp, 22); op_g43P(g, v); }
    stv<0>(s4, tbLA, v);
    __syncthreads();

    ldv<3>(s4, tbBO, v);
    { G16P g = ldGp(sGp, 23); op_qlowP(g, v); }
    { G16P g = ldGp(sGp, 24); op_qhighP(g, v); }
    stv<3>(s4, tbBO, v);
    __syncthreads();

    // final pass: last two gates + squared/normalized output (no store back)
    ldv<7>(s4, tbCO, v);
    { G16P g = ldGp(sGp, 25); op_qlowP(g, v); }
    { G16P g = ldGp(sGp, 26); op_qhighP(g, v); }
    {
        float inv = pinv[0];
        ull invp = pk2(inv, inv);
        float* ob = out + (size_t)b * OUTN;
        #pragma unroll
        for (int q = 0; q < 16; q++) {
            int j = (tbCO | (q << 7)) << 2;
            if (j >= OUT_BASE) {
                ulonglong2 r;
                r.x = f2mul(f2mul(v[q].x, v[q].x), invp);
                r.y = f2mul(f2mul(v[q].y, v[q].y), invp);
                *(ulonglong2*)(ob + (j - OUT_BASE)) = r;
            }
        }
    }
}

extern "C" void kernel_launch(void* const* d_in, const int* in_sizes, int n_in,
                              void* d_out, int out_size) {
    const float* in   = (const float*)d_in[0];
    const float* w    = (const float*)d_in[1];
    const float* bias = (const float*)d_in[2];
    float* out = (float*)d_out;
    int B = in_sizes[0] / DIM;   // 512

    const int smem_bytes = (DIM + 896 + 448 + 8 + 8) * (int)sizeof(float);  // ~71 KB
    cudaFuncSetAttribute(qnn_main, cudaFuncAttributeMaxDynamicSharedMemorySize, smem_bytes);

    qnn_prep<<<1, 32>>>(w, bias);
    qnn_main<<<B, TPB, smem_bytes>>>(in, out);
}

// round 5
// speedup vs baseline: 1.2339x; 1.2075x over previous
#include <cuda_runtime.h>

#define DIM 16384
#define OUTN 1000
#define TPB 256

typedef unsigned long long ull;

// 26 fused two-qubit gate matrices (4x4 each): e_k=k, o_k=7+k, f_k=14+k, p_k=21+k
__device__ float d_G[448];

// ---------------------------------------------------------------------------
// Prep: build fused gates (verified correct in R3/R4).
// ---------------------------------------------------------------------------
__global__ void qnn_prep(const float* __restrict__ w, const float* __restrict__ bias) {
    int g = threadIdx.x;
    if (g >= 26) return;
    int stage, p;
    if (g < 7)       { stage = 0; p = g; }
    else if (g < 13) { stage = 1; p = g - 7; }
    else if (g < 20) { stage = 2; p = g - 13; }
    else             { stage = 3; p = g - 20; }
    int l = stage >> 1;
    int par = stage & 1;
    int i = par ? (11 - 2 * p) : (12 - 2 * p);

    float thH = 0.5f * w[l * 26 + i * 2 + 0];
    float thL = 0.5f * w[l * 26 + i * 2 + 1];
    float A[4] = { cosf(thH), -sinf(thH), sinf(thH), cosf(thH) };
    float B[4] = { cosf(thL), -sinf(thL), sinf(thL), cosf(thL) };
    float G[16];
    for (int mp = 0; mp < 4; mp++)
        for (int m = 0; m < 4; m++) {
            float v = A[(mp >> 1) * 2 + (m >> 1)] * B[(mp & 1) * 2 + (m & 1)];
            G[mp * 4 + m] = (m == 3) ? -v : v;   // CZ applied first
        }
    if (stage == 0) {
        float bH = 0.5f * bias[i], bL = 0.5f * bias[i + 1];
        float Ab[4] = { cosf(bH), -sinf(bH), sinf(bH), cosf(bH) };
        float Bb[4] = { cosf(bL), -sinf(bL), sinf(bL), cosf(bL) };
        float Gb[16];
        for (int mp = 0; mp < 4; mp++)
            for (int m = 0; m < 4; m++)
                Gb[mp * 4 + m] = Ab[(mp >> 1) * 2 + (m >> 1)] * Bb[(mp & 1) * 2 + (m & 1)];
        float GG[16];
        for (int a = 0; a < 4; a++)
            for (int c = 0; c < 4; c++) {
                float s = 0.f;
                for (int k = 0; k < 4; k++) s += G[a * 4 + k] * Gb[k * 4 + c];
                GG[a * 4 + c] = s;               // apply bias first
            }
        for (int x = 0; x < 16; x++) G[x] = GG[x];
    }
    for (int x = 0; x < 16; x++) d_G[(stage * 7 + p) * 16 + x] = G[x];
}

// ---------------------------------------------------------------------------
// GF(2)-linear swizzle: bank bits = P&7 XOR g(P bits 3..6), with
// g(e3)=001, g(e4)=010, g(e5)=011, g(e6)=110 — chosen so every tile pattern's
// 3 phase-varying bits map to 3 independent bank-bit vectors (conflict-free).
// Linear => swzF(a|b) = swzF(a)^swzF(b) for disjoint bits (per-q constants).
// ---------------------------------------------------------------------------
__host__ __device__ __forceinline__ constexpr int swzF(int P) {
    return P ^ ( (((P >> 3) ^ (P >> 5)) & 1)
               | ((((P >> 4) ^ (P >> 5) ^ (P >> 6)) & 1) << 1)
               | (((P >> 6) & 1) << 2) );
}

// ---------------------------------------------------------------------------
// Packed f32x2 helpers (FFMA2 — ptxas never emits from C++)
// ---------------------------------------------------------------------------
__device__ __forceinline__ ull f2mul(ull a, ull b) {
    ull d; asm("mul.rn.f32x2 %0, %1, %2;" : "=l"(d) : "l"(a), "l"(b)); return d;
}
__device__ __forceinline__ ull f2fma(ull a, ull b, ull c) {
    ull d; asm("fma.rn.f32x2 %0, %1, %2, %3;" : "=l"(d) : "l"(a), "l"(b), "l"(c)); return d;
}
__device__ __forceinline__ void up2(ull a, float& x, float& y) {
    asm("mov.b64 {%0, %1}, %2;" : "=f"(x), "=f"(y) : "l"(a));
}
__device__ __forceinline__ ull pk2(float x, float y) {
    ull a; asm("mov.b64 %0, {%1, %2};" : "=l"(a) : "f"(x), "f"(y)); return a;
}

struct G16  { float g[16]; };
struct G16P { ull   g[16]; };

__device__ __forceinline__ G16 ldGm(const float* sG, int i) {
    G16 r;
    #pragma unroll
    for (int x = 0; x < 16; x++) r.g[x] = sG[i * 16 + x];
    return r;
}
__device__ __forceinline__ G16P ldGp(const ull* sGp, int i) {
    G16P r;
    #pragma unroll
    for (int x = 0; x < 16; x++) r.g[x] = sGp[i * 16 + x];
    return r;
}

__device__ __forceinline__ void gate4(const G16& G, float& a, float& b, float& c, float& d) {
    float x = a, y = b, z = c, w = d;
    a = G.g[0]  * x + G.g[1]  * y + G.g[2]  * z + G.g[3]  * w;
    b = G.g[4]  * x + G.g[5]  * y + G.g[6]  * z + G.g[7]  * w;
    c = G.g[8]  * x + G.g[9]  * y + G.g[10] * z + G.g[11] * w;
    d = G.g[12] * x + G.g[13] * y + G.g[14] * z + G.g[15] * w;
}
__device__ __forceinline__ void gate4p(const G16P& G, ull& a, ull& b, ull& c, ull& d) {
    ull x = a, y = b, z = c, w = d;
    a = f2fma(G.g[3],  w, f2fma(G.g[2],  z, f2fma(G.g[1],  y, f2mul(G.g[0],  x))));
    b = f2fma(G.g[7],  w, f2fma(G.g[6],  z, f2fma(G.g[5],  y, f2mul(G.g[4],  x))));
    c = f2fma(G.g[11], w, f2fma(G.g[10], z, f2fma(G.g[9],  y, f2mul(G.g[8],  x))));
    d = f2fma(G.g[15], w, f2fma(G.g[14], z, f2fma(G.g[13], y, f2mul(G.g[12], x))));
}

// gate on amp bits (1,0): mixes inside the float4 -> scalar path
__device__ __forceinline__ void op_vecS(const G16& G, ulonglong2 v[16]) {
    #pragma unroll
    for (int q = 0; q < 16; q++) {
        float a, b, c, d;
        up2(v[q].x, a, b); up2(v[q].y, c, d);
        gate4(G, a, b, c, d);
        v[q].x = pk2(a, b); v[q].y = pk2(c, d);
    }
}
// gate on q bits (1,0)
__device__ __forceinline__ void op_qlowP(const G16P& G, ulonglong2 v[16]) {
    #pragma unroll
    for (int h = 0; h < 16; h += 4) {
        gate4p(G, v[h].x, v[h+1].x, v[h+2].x, v[h+3].x);
        gate4p(G, v[h].y, v[h+1].y, v[h+2].y, v[h+3].y);
    }
}
// gate on q bits (3,2)
__device__ __forceinline__ void op_qhighP(const G16P& G, ulonglong2 v[16]) {
    #pragma unroll
    for (int j = 0; j < 4; j++) {
        gate4p(G, v[j].x, v[j+4].x, v[j+8].x, v[j+12].x);
        gate4p(G, v[j].y, v[j+4].y, v[j+8].y, v[j+12].y);
    }
}
// gate on q bits (2,1)
__device__ __forceinline__ void op_g43P(const G16P& G, ulonglong2 v[16]) {
    #pragma unroll
    for (int j3 = 0; j3 < 2; j3++)
        #pragma unroll
        for (int j0 = 0; j0 < 2; j0++) {
            int b0 = j0 + 8 * j3;
            gate4p(G, v[b0].x, v[b0+2].x, v[b0+4].x, v[b0+6].x);
            gate4p(G, v[b0].y, v[b0+2].y, v[b0+4].y, v[b0+6].y);
        }
}
// gate hi = q bit0, lo = amp bit1 (.x/.y halves)
__device__ __forceinline__ void op_g21P(const G16P& G, ulonglong2 v[16]) {
    #pragma unroll
    for (int h = 0; h < 16; h += 2)
        gate4p(G, v[h].x, v[h].y, v[h+1].x, v[h+1].y);
}
// same, upper half only (q >= 8, amp bit13 = 1)
__device__ __forceinline__ void op_g21P_hi(const G16P& G, ulonglong2 v[16]) {
    #pragma unroll
    for (int h = 8; h < 16; h += 2)
        gate4p(G, v[h].x, v[h].y, v[h+1].x, v[h+1].y);
}

// q placed at float4-index bits [S, S+3]; per-q offset is compile-time XOR
template<int S>
__device__ __forceinline__ void ldvS(const ulonglong2* s4, int base, ulonglong2 v[16]) {
    #pragma unroll
    for (int q = 0; q < 16; q++) v[q] = s4[base ^ swzF(q << S)];
}
template<int S>
__device__ __forceinline__ void stvS(ulonglong2* s4, int base, const ulonglong2 v[16]) {
    #pragma unroll
    for (int q = 0; q < 16; q++) s4[base ^ swzF(q << S)] = v[q];
}
// T6 tile: q bits 0,1 -> P bits 0,1; q bits 2,3 -> P bits 10,11 (g() untouched)
__device__ __forceinline__ void ldv6(const ulonglong2* s4, int base, ulonglong2 v[16]) {
    #pragma unroll
    for (int q = 0; q < 16; q++) v[q] = s4[base ^ ((q & 3) | ((q >> 2) << 10))];
}
__device__ __forceinline__ void stv6_hi(ulonglong2* s4, int base, const ulonglong2 v[16]) {
    #pragma unroll
    for (int q = 8; q < 16; q++) s4[base ^ ((q & 3) | ((q >> 2) << 10))] = v[q];
}

// ---------------------------------------------------------------------------
// Main kernel: 1 CTA/row, 9 fused passes (cross-stage DAG schedule),
// dead-cone trimming on passes 6-9. 2 CTAs/SM.
// ---------------------------------------------------------------------------
__global__ void __launch_bounds__(TPB, 2) qnn_main(const float* __restrict__ in,
                                                   float* __restrict__ out) {
    extern __shared__ float sm[];
    ulonglong2* s4 = (ulonglong2*)sm;            // 16384 floats state
    ull*   sGp  = (ull*)(sm + DIM);              // 448 splatted gate coeffs
    float* sGs  = sm + DIM + 896;                // 448 scalar gate coeffs
    float* red  = sGs + 448;
    float* pinv = red + 8;
    const int t = threadIdx.x;
    const int b = blockIdx.x;

    for (int x = t; x < 448; x += TPB) {
        float g = d_G[x];
        sGs[x] = g;
        sGp[x] = pk2(g, g);
    }

    // ---- P1: global load in T1 order (256B contiguous per thread) + ss
    const ulonglong2* g4 = (const ulonglong2*)(in + (size_t)b * DIM);
    ulonglong2 v[16];
    ull ssp = 0ull;
    #pragma unroll
    for (int q = 0; q < 16; q++) {
        v[q] = g4[(t << 4) | q];
        ssp = f2fma(v[q].x, v[q].x, ssp);
        ssp = f2fma(v[q].y, v[q].y, ssp);
    }
    float s0, s1; up2(ssp, s0, s1);
    float ss = s0 + s1;
    #pragma unroll
    for (int o = 16; o; o >>= 1) ss += __shfl_xor_sync(0xffffffffu, ss, o);
    if ((t & 31) == 0) red[t >> 5] = ss;
    __syncthreads();                      // covers gate tables + red
    if (t == 0) {
        float tot = 0.f;
        #pragma unroll
        for (int k = 0; k < 8; k++) tot += red[k];
        pinv[0] = 1.0f / tot;             // read only in P9, after barriers
    }

    // P1 gates, tile {0,1,2,3,4,5}: e0,e1,e2 then o0,o1
    { G16  g = ldGm(sGs, 0); op_vecS(g, v); }          // e0 (1,0)
    { G16P g = ldGp(sGp, 1); op_qlowP(g, v); }         // e1 (3,2)
    { G16P g = ldGp(sGp, 2); op_qhighP(g, v); }        // e2 (5,4)
    { G16P g = ldGp(sGp, 7); op_g21P(g, v); }          // o0 (2,1)
    { G16P g = ldGp(sGp, 8); op_g43P(g, v); }          // o1 (4,3)
    { int base = swzF(t << 4); stvS<0>(s4, base, v); }
    __syncthreads();

    // ---- P2, tile {0,1,6,7,8,9}: e3,e4 then o3
    { int base = swzF((t & 15) | ((t >> 4) << 8));
      ldvS<4>(s4, base, v);
      { G16P g = ldGp(sGp, 3);  op_qlowP(g, v); }      // e3 (7,6)
      { G16P g = ldGp(sGp, 4);  op_qhighP(g, v); }     // e4 (9,8)
      { G16P g = ldGp(sGp, 10); op_g43P(g, v); }       // o3 (8,7)
      stvS<4>(s4, base, v); }
    __syncthreads();

    // ---- P3, tile {0,1,10,11,12,13}: e5,e6 then o5
    { int base = swzF(t);
      ldvS<8>(s4, base, v);
      { G16P g = ldGp(sGp, 5);  op_qlowP(g, v); }      // e5 (11,10)
      { G16P g = ldGp(sGp, 6);  op_qhighP(g, v); }     // e6 (13,12)
      { G16P g = ldGp(sGp, 12); op_g43P(g, v); }       // o5 (12,11)
      stvS<8>(s4, base, v); }
    __syncthreads();

    // ---- P4, tile {0,1,4,5,6,7}: o2 then f2,f3
    { int base = swzF((t & 3) | ((t >> 2) << 6));
      ldvS<2>(s4, base, v);
      { G16P g = ldGp(sGp, 9);  op_g43P(g, v); }       // o2 (6,5)
      { G16P g = ldGp(sGp, 16); op_qlowP(g, v); }      // f2 (5,4)
      { G16P g = ldGp(sGp, 17); op_qhighP(g, v); }     // f3 (7,6)
      stvS<2>(s4, base, v); }
    __syncthreads();

    // ---- P5, tile {0,1,8,9,10,11}: o4 then f4,f5
    { int base = swzF((t & 63) | ((t >> 6) << 10));
      ldvS<6>(s4, base, v);
      { G16P g = ldGp(sGp, 11); op_g43P(g, v); }       // o4 (10,9)
      { G16P g = ldGp(sGp, 18); op_qlowP(g, v); }      // f4 (9,8)
      { G16P g = ldGp(sGp, 19); op_qhighP(g, v); }     // f5 (11,10)
      stvS<6>(s4, base, v); }
    __syncthreads();

    // ---- P6, tile {0,1,2,3,12,13}: f0,f1,f6 then p0; store bit13=1 half only
    { int base = swzF(t << 2);
      ldv6(s4, base, v);
      { G16  g = ldGm(sGs, 14); op_vecS(g, v); }       // f0 (1,0)
      { G16P g = ldGp(sGp, 15); op_qlowP(g, v); }      // f1 (3,2)
      { G16P g = ldGp(sGp, 20); op_qhighP(g, v); }     // f6 (13,12)
      { G16P g = ldGp(sGp, 21); op_g21P_hi(g, v); }    // p0 (2,1), bit13=1 only
      stv6_hi(s4, base, v); }
    __syncthreads();

    // ---- P7, tile {0,1,3,4,5,6}: p1,p2 — only amps with bit13=1 (t>=128)
    if (t >= 128) {
      int base = swzF((t & 1) | ((t >> 1) << 5));
      ldvS<1>(s4, base, v);
      { G16P g = ldGp(sGp, 22); op_qlowP(g, v); }      // p1 (4,3)
      { G16P g = ldGp(sGp, 23); op_qhighP(g, v); }     // p2 (6,5)
      stvS<1>(s4, base, v);
    }
    __syncthreads();

    // ---- P8, tile {0,1,7,8,9,10}: p3,p4 — only bit13=1 (t>=128)
    if (t >= 128) {
      int base = swzF((t & 31) | ((t >> 5) << 9));
      ldvS<5>(s4, base, v);
      { G16P g = ldGp(sGp, 24); op_qlowP(g, v); }      // p3 (8,7)
      { G16P g = ldGp(sGp, 25); op_qhighP(g, v); }     // p4 (10,9)
      stvS<5>(s4, base, v);
    }
    __syncthreads();

    // ---- P9 (trimmed): p5 (12,11) row m=3 only, then output.
    // Output amps j = 4*(t + 3840) for t>=6; inputs at q in {9,11,13,15}.
    if (t >= 6) {
        int base = swzF(t);
        ulonglong2 v9  = s4[base ^ swzF(9  << 8)];
        ulonglong2 v11 = s4[base ^ swzF(11 << 8)];
        ulonglong2 v13 = s4[base ^ swzF(13 << 8)];
        ulonglong2 v15 = s4[base ^ swzF(15 << 8)];
        G16P g = ldGp(sGp, 26);                        // p5
        ull dx = f2fma(g.g[15], v15.x, f2fma(g.g[14], v13.x,
                 f2fma(g.g[13], v11.x, f2mul(g.g[12], v9.x))));
        ull dy = f2fma(g.g[15], v15.y, f2fma(g.g[14], v13.y,
                 f2fma(g.g[13], v11.y, f2mul(g.g[12], v9.y))));
        float inv = pinv[0];
        ull invp = pk2(inv, inv);
        ulonglong2 r;
        r.x = f2mul(f2mul(dx, dx), invp);
        r.y = f2mul(f2mul(dy, dy), invp);
        *(ulonglong2*)(out + (size_t)b * OUTN + 4 * t - 24) = r;
    }
}

extern "C" void kernel_launch(void* const* d_in, const int* in_sizes, int n_in,
                              void* d_out, int out_size) {
    const float* in   = (const float*)d_in[0];
    const float* w    = (const float*)d_in[1];
    const float* bias = (const float*)d_in[2];
    float* out = (float*)d_out;
    int B = in_sizes[0] / DIM;   // 512

    const int smem_bytes = (DIM + 896 + 448 + 8 + 8) * (int)sizeof(float);  // ~71 KB
    cudaFuncSetAttribute(qnn_main, cudaFuncAttributeMaxDynamicSharedMemorySize, smem_bytes);

    qnn_prep<<<1, 32>>>(w, bias);
    qnn_main<<<B, TPB, smem_bytes>>>(in, out);
}

// round 7
// speedup vs baseline: 1.4091x; 1.1420x over previous
#include <cuda_runtime.h>

#define DIM 16384
#define OUTN 1000
#define TPB 256

typedef unsigned long long ull;

// 26 fused two-qubit gate matrices (4x4 each): e_k=k, o_k=7+k, f_k=14+k, p_k=21+k
__device__ float d_G[448];

// ---------------------------------------------------------------------------
// Prep: build fused gates (verified correct R3-R5).
// ---------------------------------------------------------------------------
__global__ void qnn_prep(const float* __restrict__ w, const float* __restrict__ bias) {
    int g = threadIdx.x;
    if (g >= 26) return;
    int stage, p;
    if (g < 7)       { stage = 0; p = g; }
    else if (g < 13) { stage = 1; p = g - 7; }
    else if (g < 20) { stage = 2; p = g - 13; }
    else             { stage = 3; p = g - 20; }
    int l = stage >> 1;
    int par = stage & 1;
    int i = par ? (11 - 2 * p) : (12 - 2 * p);

    float thH = 0.5f * w[l * 26 + i * 2 + 0];
    float thL = 0.5f * w[l * 26 + i * 2 + 1];
    float A[4] = { cosf(thH), -sinf(thH), sinf(thH), cosf(thH) };
    float B[4] = { cosf(thL), -sinf(thL), sinf(thL), cosf(thL) };
    float G[16];
    for (int mp = 0; mp < 4; mp++)
        for (int m = 0; m < 4; m++) {
            float v = A[(mp >> 1) * 2 + (m >> 1)] * B[(mp & 1) * 2 + (m & 1)];
            G[mp * 4 + m] = (m == 3) ? -v : v;   // CZ applied first
        }
    if (stage == 0) {
        float bH = 0.5f * bias[i], bL = 0.5f * bias[i + 1];
        float Ab[4] = { cosf(bH), -sinf(bH), sinf(bH), cosf(bH) };
        float Bb[4] = { cosf(bL), -sinf(bL), sinf(bL), cosf(bL) };
        float Gb[16];
        for (int mp = 0; mp < 4; mp++)
            for (int m = 0; m < 4; m++)
                Gb[mp * 4 + m] = Ab[(mp >> 1) * 2 + (m >> 1)] * Bb[(mp & 1) * 2 + (m & 1)];
        float GG[16];
        for (int a = 0; a < 4; a++)
            for (int c = 0; c < 4; c++) {
                float s = 0.f;
                for (int k = 0; k < 4; k++) s += G[a * 4 + k] * Gb[k * 4 + c];
                GG[a * 4 + c] = s;               // apply bias first
            }
        for (int x = 0; x < 16; x++) G[x] = GG[x];
    }
    for (int x = 0; x < 16; x++) d_G[(stage * 7 + p) * 16 + x] = G[x];
}

// ---------------------------------------------------------------------------
// GF(2)-linear swizzle for the R6 tile set:
//   g(b3)=100, g(b4)=010, g(b5)=001, g(b6)=100, g(b7..b11)=0
// Per pass, the 3 phase-varying f4 bits map to 3 independent bank vectors:
//   P1 {b4,b5,b6}->{010,001,100}; P4 {b0,b1,b6}->{001,010,100};
//   P6 {b0,b3,b4}->{001,100,010}; P2/P3/P5/P7 use b0-b2 (identity).
// ---------------------------------------------------------------------------
__host__ __device__ __forceinline__ constexpr int swzF(int P) {
    return P ^ (((((P >> 3) ^ (P >> 6)) & 1) << 2)
             |  ((((P >> 4)) & 1) << 1)
             |  (((P >> 5)) & 1));
}

// ---------------------------------------------------------------------------
// Packed f32x2 helpers (FFMA2 — ptxas never emits from C++)
// ---------------------------------------------------------------------------
__device__ __forceinline__ ull f2mul(ull a, ull b) {
    ull d; asm("mul.rn.f32x2 %0, %1, %2;" : "=l"(d) : "l"(a), "l"(b)); return d;
}
__device__ __forceinline__ ull f2fma(ull a, ull b, ull c) {
    ull d; asm("fma.rn.f32x2 %0, %1, %2, %3;" : "=l"(d) : "l"(a), "l"(b), "l"(c)); return d;
}
__device__ __forceinline__ void up2(ull a, float& x, float& y) {
    asm("mov.b64 {%0, %1}, %2;" : "=f"(x), "=f"(y) : "l"(a));
}
__device__ __forceinline__ ull pk2(float x, float y) {
    ull a; asm("mov.b64 %0, {%1, %2};" : "=l"(a) : "f"(x), "f"(y)); return a;
}

struct G16  { float g[16]; };
struct G16P { ull   g[16]; };

__device__ __forceinline__ G16 ldGm(const float* sG, int i) {
    G16 r;
    #pragma unroll
    for (int x = 0; x < 16; x++) r.g[x] = sG[i * 16 + x];
    return r;
}
__device__ __forceinline__ G16P ldGp(const ull* sGp, int i) {
    G16P r;
    #pragma unroll
    for (int x = 0; x < 16; x++) r.g[x] = sGp[i * 16 + x];
    return r;
}

__device__ __forceinline__ void gate4(const G16& G, float& a, float& b, float& c, float& d) {
    float x = a, y = b, z = c, w = d;
    a = G.g[0]  * x + G.g[1]  * y + G.g[2]  * z + G.g[3]  * w;
    b = G.g[4]  * x + G.g[5]  * y + G.g[6]  * z + G.g[7]  * w;
    c = G.g[8]  * x + G.g[9]  * y + G.g[10] * z + G.g[11] * w;
    d = G.g[12] * x + G.g[13] * y + G.g[14] * z + G.g[15] * w;
}
__device__ __forceinline__ void gate4p(const G16P& G, ull& a, ull& b, ull& c, ull& d) {
    ull x = a, y = b, z = c, w = d;
    a = f2fma(G.g[3],  w, f2fma(G.g[2],  z, f2fma(G.g[1],  y, f2mul(G.g[0],  x))));
    b = f2fma(G.g[7],  w, f2fma(G.g[6],  z, f2fma(G.g[5],  y, f2mul(G.g[4],  x))));
    c = f2fma(G.g[11], w, f2fma(G.g[10], z, f2fma(G.g[9],  y, f2mul(G.g[8],  x))));
    d = f2fma(G.g[15], w, f2fma(G.g[14], z, f2fma(G.g[13], y, f2mul(G.g[12], x))));
}

// gate on amp bits (1,0): mixes inside the float4 -> scalar path
__device__ __forceinline__ void op_vecS(const G16& G, ulonglong2 v[16]) {
    #pragma unroll
    for (int q = 0; q < 16; q++) {
        float a, b, c, d;
        up2(v[q].x, a, b); up2(v[q].y, c, d);
        gate4(G, a, b, c, d);
        v[q].x = pk2(a, b); v[q].y = pk2(c, d);
    }
}
// gate on q bits (1,0)
__device__ __forceinline__ void op_qlowP(const G16P& G, ulonglong2 v[16]) {
    #pragma unroll
    for (int h = 0; h < 16; h += 4) {
        gate4p(G, v[h].x, v[h+1].x, v[h+2].x, v[h+3].x);
        gate4p(G, v[h].y, v[h+1].y, v[h+2].y, v[h+3].y);
    }
}
// gate on q bits (3,2)
__device__ __forceinline__ void op_qhighP(const G16P& G, ulonglong2 v[16]) {
    #pragma unroll
    for (int j = 0; j < 4; j++) {
        gate4p(G, v[j].x, v[j+4].x, v[j+8].x, v[j+12].x);
        gate4p(G, v[j].y, v[j+4].y, v[j+8].y, v[j+12].y);
    }
}
// gate on q bits (2,1)
__device__ __forceinline__ void op_g43P(const G16P& G, ulonglong2 v[16]) {
    #pragma unroll
    for (int j3 = 0; j3 < 2; j3++)
        #pragma unroll
        for (int j0 = 0; j0 < 2; j0++) {
            int b0 = j0 + 8 * j3;
            gate4p(G, v[b0].x, v[b0+2].x, v[b0+4].x, v[b0+6].x);
            gate4p(G, v[b0].y, v[b0+2].y, v[b0+4].y, v[b0+6].y);
        }
}
// gate hi = q bit0, lo = amp bit1 (.x/.y halves)
__device__ __forceinline__ void op_g21P(const G16P& G, ulonglong2 v[16]) {
    #pragma unroll
    for (int h = 0; h < 16; h += 2)
        gate4p(G, v[h].x, v[h].y, v[h+1].x, v[h+1].y);
}

// q placed at float4-index bits [S, S+3]; per-q offset is a compile-time XOR
template<int S>
__device__ __forceinline__ void ldvS(const ulonglong2* s4, int base, ulonglong2 v[16]) {
    #pragma unroll
    for (int q = 0; q < 16; q++) v[q] = s4[base ^ swzF(q << S)];
}
template<int S>
__device__ __forceinline__ void stvS(ulonglong2* s4, int base, const ulonglong2 v[16]) {
    #pragma unroll
    for (int q = 0; q < 16; q++) s4[base ^ swzF(q << S)] = v[q];
}
// P3 store: only q>=8 (amp bit13 = f4 bit11 = q bit3 set)
__device__ __forceinline__ void stv8hi(ulonglong2* s4, int base, const ulonglong2 v[16]) {
    #pragma unroll
    for (int q = 8; q < 16; q++) s4[base ^ swzF(q << 8)] = v[q];
}
// P6 irregular tile: q bits 0,1 -> f4 bits 1,2; q bits 2,3 -> f4 bits 5,6
__device__ __forceinline__ void ldv6(const ulonglong2* s4, int base, ulonglong2 v[16]) {
    #pragma unroll
    for (int q = 0; q < 16; q++)
        v[q] = s4[base ^ swzF(((q & 3) << 1) | ((q >> 2) << 5))];
}
__device__ __forceinline__ void stv6(ulonglong2* s4, int base, const ulonglong2 v[16]) {
    #pragma unroll
    for (int q = 0; q < 16; q++)
        s4[base ^ swzF(((q & 3) << 1) | ((q >> 2) << 5))] = v[q];
}

// ---------------------------------------------------------------------------
// Main kernel: 1 CTA/row, 7 fused passes, dead-cone (bit13=1) from P4 on.
// ---------------------------------------------------------------------------
__global__ void __launch_bounds__(TPB, 2) qnn_main(const float* __restrict__ in,
                                                   float* __restrict__ out) {
    extern __shared__ float sm[];
    ulonglong2* s4 = (ulonglong2*)sm;            // 16384 floats state
    ull*   sGp  = (ull*)(sm + DIM);              // 448 splatted gate coeffs
    float* sGs  = sm + DIM + 896;                // 448 scalar gate coeffs
    float* red  = sGs + 448;
    float* pinv = red + 8;
    const int t = threadIdx.x;
    const int b = blockIdx.x;

    for (int x = t; x < 448; x += TPB) {
        float g = d_G[x];
        sGs[x] = g;
        sGp[x] = pk2(g, g);
    }

    // ---- P1: global load in tile order + sum-of-squares
    const ulonglong2* g4 = (const ulonglong2*)(in + (size_t)b * DIM);
    ulonglong2 v[16];
    ull ssp = 0ull;
    #pragma unroll
    for (int q = 0; q < 16; q++) {
        v[q] = g4[(t << 4) | q];
        ssp = f2fma(v[q].x, v[q].x, ssp);
        ssp = f2fma(v[q].y, v[q].y, ssp);
    }
    float s0, s1; up2(ssp, s0, s1);
    float ss = s0 + s1;
    #pragma unroll
    for (int o = 16; o; o >>= 1) ss += __shfl_xor_sync(0xffffffffu, ss, o);
    if ((t & 31) == 0) red[t >> 5] = ss;
    __syncthreads();                      // barrier 1: gate tables + red
    if (t == 0) {
        float tot = 0.f;
        #pragma unroll
        for (int k = 0; k < 8; k++) tot += red[k];
        pinv[0] = 1.0f / tot;             // read only in P7, after barriers
    }

    // P1 gates, tile {0,1,2,3,4,5}: e0,e1,e2,o0,o1,f0,f1,p0  (8 gates)
    { G16  g = ldGm(sGs, 0);  op_vecS(g, v); }         // e0 (1,0)
    { G16P g = ldGp(sGp, 1);  op_qlowP(g, v); }        // e1 (3,2)
    { G16P g = ldGp(sGp, 2);  op_qhighP(g, v); }       // e2 (5,4)
    { G16P g = ldGp(sGp, 7);  op_g21P(g, v); }         // o0 (2,1)
    { G16P g = ldGp(sGp, 8);  op_g43P(g, v); }         // o1 (4,3)
    { G16  g = ldGm(sGs, 14); op_vecS(g, v); }         // f0 (1,0)
    { G16P g = ldGp(sGp, 15); op_qlowP(g, v); }        // f1 (3,2)
    { G16P g = ldGp(sGp, 21); op_g21P(g, v); }         // p0 (2,1)
    { int base = swzF(t << 4); stvS<0>(s4, base, v); }
    __syncthreads();                      // barrier 2

    // ---- P2, tile {0,1,6,7,8,9}: e3,e4,o3
    { int base = swzF((t & 15) | ((t >> 4) << 8));
      ldvS<4>(s4, base, v);
      { G16P g = ldGp(sGp, 3);  op_qlowP(g, v); }      // e3 (7,6)
      { G16P g = ldGp(sGp, 4);  op_qhighP(g, v); }     // e4 (9,8)
      { G16P g = ldGp(sGp, 10); op_g43P(g, v); }       // o3 (8,7)
      stvS<4>(s4, base, v); }
    __syncthreads();                      // barrier 3

    // ---- P3, tile {0,1,10,11,12,13}: e5,e6,o5,f6; store bit13=1 half only
    { int base = swzF(t);
      ldvS<8>(s4, base, v);
      { G16P g = ldGp(sGp, 5);  op_qlowP(g, v); }      // e5 (11,10)
      { G16P g = ldGp(sGp, 6);  op_qhighP(g, v); }     // e6 (13,12)
      { G16P g = ldGp(sGp, 12); op_g43P(g, v); }       // o5 (12,11)
      { G16P g = ldGp(sGp, 20); op_qhighP(g, v); }     // f6 (13,12)
      stv8hi(s4, base, v); }
    __syncthreads();                      // barrier 4

    // ---- P4, tile {0,1,4,5,6,7}: o2,f2,f3,p2 — bit13=1 only (t>=128)
    if (t >= 128) {
      int base = swzF((t & 3) | ((t >> 2) << 6));      // f4 bit11 = t bit7 = 1
      ldvS<2>(s4, base, v);
      { G16P g = ldGp(sGp, 9);  op_g43P(g, v); }       // o2 (6,5)
      { G16P g = ldGp(sGp, 16); op_qlowP(g, v); }      // f2 (5,4)
      { G16P g = ldGp(sGp, 17); op_qhighP(g, v); }     // f3 (7,6)
      { G16P g = ldGp(sGp, 23); op_g43P(g, v); }       // p2 (6,5)
      stvS<2>(s4, base, v);
    }
    __syncthreads();                      // barrier 5

    // ---- P5, tile {0,1,8,9,10,11}: o4,f4,f5,p4 — bit13=1 only (t>=128)
    if (t >= 128) {
      int base = swzF((t & 63) | ((t >> 6) << 10));    // f4 bit11 = t bit7 = 1
      ldvS<6>(s4, base, v);
      { G16P g = ldGp(sGp, 11); op_g43P(g, v); }       // o4 (10,9)
      { G16P g = ldGp(sGp, 18); op_qlowP(g, v); }      // f4 (9,8)
      { G16P g = ldGp(sGp, 19); op_qhighP(g, v); }     // f5 (11,10)
      { G16P g = ldGp(sGp, 25); op_g43P(g, v); }       // p4 (10,9)
      stvS<6>(s4, base, v);
    }
    __syncthreads();                      // barrier 6

    // ---- P6, tile {0,1,3,4,7,8}: p1,p3 — bit13=1 only (t>=128)
    if (t >= 128) {
      int tp = t & 127;
      int base = swzF((tp & 1) | (((tp >> 1) & 3) << 3)
                      | ((tp >> 3) << 7) | 2048);      // f4 bit11 = 1
      ldv6(s4, base, v);
      { G16P g = ldGp(sGp, 22); op_qlowP(g, v); }      // p1 (4,3)
      { G16P g = ldGp(sGp, 24); op_qhighP(g, v); }     // p3 (8,7)
      stv6(s4, base, v);
    }
    __syncthreads();                      // barrier 7

    // ---- P7: p5 (12,11) row m=3 only + output (amps j >= 15384, bit13=1)
    if (t >= 6) {
        ulonglong2 v0 = s4[swzF(2304 + t)];   // (b10,b9)=(0,0)
        ulonglong2 v1 = s4[swzF(2816 + t)];   // (0,1)
        ulonglong2 v2 = s4[swzF(3328 + t)];   // (1,0)
        ulonglong2 v3 = s4[swzF(3840 + t)];   // (1,1) = output row
        G16P g = ldGp(sGp, 26);                        // p5
        ull dx = f2fma(g.g[15], v3.x, f2fma(g.g[14], v2.x,
                 f2fma(g.g[13], v1.x, f2mul(g.g[12], v0.x))));
        ull dy = f2fma(g.g[15], v3.y, f2fma(g.g[14], v2.y,
                 f2fma(g.g[13], v1.y, f2mul(g.g[12], v0.y))));
        float inv = pinv[0];
        ull invp = pk2(inv, inv);
        ulonglong2 r;
        r.x = f2mul(f2mul(dx, dx), invp);
        r.y = f2mul(f2mul(dy, dy), invp);
        *(ulonglong2*)(out + (size_t)b * OUTN + 4 * t - 24) = r;
    }
}

extern "C" void kernel_launch(void* const* d_in, const int* in_sizes, int n_in,
                              void* d_out, int out_size) {
    const float* in   = (const float*)d_in[0];
    const float* w    = (const float*)d_in[1];
    const float* bias = (const float*)d_in[2];
    float* out = (float*)d_out;
    int B = in_sizes[0] / DIM;   // 512

    const int smem_bytes = (DIM + 896 + 448 + 8 + 8) * (int)sizeof(float);  // ~71 KB
    cudaFuncSetAttribute(qnn_main, cudaFuncAttributeMaxDynamicSharedMemorySize, smem_bytes);

    qnn_prep<<<1, 32>>>(w, bias);
    qnn_main<<<B, TPB, smem_bytes>>>(in, out);
}